// round 5
// baseline (speedup 1.0000x reference)
#include <cuda_runtime.h>
#include <cuda_fp16.h>
#include <math.h>
#include <cstdint>

#define BB 32
#define TT 8
#define NN 512
#define FF 4
#define HH 64
#define ROWS (BB*TT*NN)
#define BTN  (BB*TT)
#define LOG2E 1.4426950408889634f

// ---------------- scratch (static device globals; no allocation) ----------------
__device__ __half d_WxT[(size_t)BTN*HH*NN];   // 16.8 MB [bt][h][j] fp16
__device__ float  d_asrc[ROWS];               // pre-scaled by log2(e)
__device__ float  d_adst[ROWS];               // pre-scaled by log2(e)
__device__ float  d_gates[(size_t)ROWS*12];

// ============ K1: WxT fp16 + a_src/a_dst (log2-scaled) ===========================
__global__ void k_proj(const float* __restrict__ x, const float* __restrict__ gat_W,
                       const float* __restrict__ att_src, const float* __restrict__ att_dst)
{
    __shared__ float4 sx4[NN];
    __shared__ float  sW[256];
    __shared__ float  su[4], sv[4];
    int bt = blockIdx.x, tid = threadIdx.x;
    int w = tid >> 5, lane = tid & 31;

    const float4* gx = (const float4*)(x + (size_t)bt*NN*FF);
    sx4[tid] = gx[tid];
    sx4[tid + 256] = gx[tid + 256];
    if (tid < 256) sW[tid] = gat_W[tid];
    __syncthreads();

    if (w == 0) {
        float as0 = __ldg(&att_src[lane]), as1 = __ldg(&att_src[32 + lane]);
        float ad0 = __ldg(&att_dst[lane]), ad1 = __ldg(&att_dst[32 + lane]);
        #pragma unroll
        for (int f = 0; f < 4; f++) {
            float uu = sW[f*64 + lane]*as0 + sW[f*64 + 32 + lane]*as1;
            float vv = sW[f*64 + lane]*ad0 + sW[f*64 + 32 + lane]*ad1;
            #pragma unroll
            for (int o = 16; o > 0; o >>= 1) {
                uu += __shfl_xor_sync(0xffffffffu, uu, o);
                vv += __shfl_xor_sync(0xffffffffu, vv, o);
            }
            if (lane == 0) { su[f] = uu*LOG2E; sv[f] = vv*LOG2E; }
        }
    }
    __syncthreads();

    __half2* wt = (__half2*)(d_WxT + (size_t)bt*HH*NN);
    for (int h = w; h < 64; h += 8) {
        float w0 = sW[h], w1 = sW[64 + h], w2 = sW[128 + h], w3 = sW[192 + h];
        #pragma unroll
        for (int jc = 0; jc < 8; jc++) {
            int j = jc*64 + lane*2;
            float4 a = sx4[j], b = sx4[j + 1];
            float wx0 = a.x*w0 + a.y*w1 + a.z*w2 + a.w*w3;
            float wx1 = b.x*w0 + b.y*w1 + b.z*w2 + b.w*w3;
            wt[(h*NN + j) >> 1] = __floats2half2_rn(wx0, wx1);
        }
    }
    #pragma unroll
    for (int r = 0; r < 2; r++) {
        int j = tid + r*256;
        float4 a = sx4[j];
        d_asrc[bt*NN + j] = a.x*su[0] + a.y*su[1] + a.z*su[2] + a.w*su[3];
        d_adst[bt*NN + j] = a.x*sv[0] + a.y*sv[1] + a.z*sv[2] + a.w*sv[3];
    }
}

// ===== K2: fused mask(reg) + softmax(fp16x2 ex2) + HMMA GEMM + gates, occ=2 =====
#define SP     0          /* P half tile: 128 x 512B (fp16, XOR-swizzled); D reuses */
#define SB     65536      /* B half tile: 64 x 512B */
#define SASRC  98304      /* 512 half = 1024 */
#define SWIH   99328      /* 768 f32 = 3072 */
#define SBIAS  102400     /* 64 f32 */
#define SBIH   102656     /* 16 f32 */
#define SL     102720     /* 128 f32 */
#define SME_TOTAL 103232
#define DSTRIDE 66

__device__ __forceinline__ void mma16816(float* d, const uint32_t* a, const uint32_t* b)
{
    asm volatile("mma.sync.aligned.m16n8k16.row.col.f32.f16.f16.f32 "
        "{%0,%1,%2,%3}, {%4,%5,%6,%7}, {%8,%9}, {%0,%1,%2,%3};"
        : "+f"(d[0]), "+f"(d[1]), "+f"(d[2]), "+f"(d[3])
        : "r"(a[0]), "r"(a[1]), "r"(a[2]), "r"(a[3]), "r"(b[0]), "r"(b[1]));
}

__global__ void __launch_bounds__(256, 2)
k_attn(const float* __restrict__ adj, const float* __restrict__ gat_bias,
       const float* __restrict__ W_ih, const float* __restrict__ b_ih)
{
    extern __shared__ char smem[];
    float* sWih  = (float*)(smem + SWIH);
    float* sBias = (float*)(smem + SBIAS);
    float* sBih  = (float*)(smem + SBIH);
    float* sLf   = (float*)(smem + SL);

    int bt    = blockIdx.x >> 2;
    int mtile = blockIdx.x & 3;
    int tid   = threadIdx.x;
    int w     = tid >> 5, lane = tid & 31;

    // ---- small stages ----
    for (int i = tid; i < 768; i += 256) sWih[i] = __ldg(&W_ih[i]);
    if (tid < 64) sBias[tid] = __ldg(&gat_bias[tid]);
    if (tid < 12) sBih[tid]  = __ldg(&b_ih[tid]);
    if (tid < 256) {
        float2 v = *(const float2*)&d_asrc[bt*NN + tid*2];
        ((__half2*)(smem + SASRC))[tid] = __floats2half2_rn(v.x, v.y);
    }

    // ---- register-resident mask build ----
    // lane L of warp w builds 8 words: row i = mtile*128 + w*16 + (L&15),
    // jtb = 2c + (L>>4)  (c = 0..7). Loads are two 64B segments per warp instr.
    uint32_t mw[8];
    {
        const float* adjbt = adj + (size_t)bt*NN*NN;
        int ii = mtile*128 + w*16 + (lane & 15);
        int par = lane >> 4;
        #pragma unroll
        for (int c = 0; c < 8; c++) {
            int jtb = 2*c + par;
            const float* col = adjbt + (size_t)(jtb*32)*NN + ii;
            uint32_t word = 0;
            #pragma unroll
            for (int jl = 0; jl < 32; jl++)
                word |= (__ldg(&col[(size_t)jl*NN]) != 0.0f ? 1u : 0u) << jl;
            if ((ii >> 5) == jtb) word |= 1u << (ii & 31);
            mw[c] = word;
        }
    }
    __syncthreads();

    // ---- warp-uniform max of (log2-scaled) a_src ----
    float sxmax;
    {
        const __half2* sa2 = (const __half2*)(smem + SASRC);
        __half2 mx = __floats2half2_rn(-60000.f, -60000.f);
        #pragma unroll
        for (int k = 0; k < 8; k++) mx = __hmax2(mx, sa2[lane*8 + k]);
        float m = fmaxf(__low2float(mx), __high2float(mx));
        #pragma unroll
        for (int o = 16; o > 0; o >>= 1) m = fmaxf(m, __shfl_xor_sync(0xffffffffu, m, o));
        sxmax = m;
    }

    const __half2 c02 = __floats2half2_rn(0.2f, 0.2f);
    float lpr[16];
    #pragma unroll
    for (int qi = 0; qi < 16; qi++) lpr[qi] = 0.0f;

    float acc[2][4][4];
    #pragma unroll
    for (int mf = 0; mf < 2; mf++)
        #pragma unroll
        for (int nf = 0; nf < 4; nf++)
            #pragma unroll
            for (int r = 0; r < 4; r++) acc[mf][nf][r] = 0.0f;

    int mg = w & 3, ng = w >> 2;
    int mbase = mg*32, nbase = ng*32;
    int tm = lane >> 2;
    int tc4 = (lane & 3)*4;

    #pragma unroll 1
    for (int hv = 0; hv < 2; hv++) {
        // ---- stage B half: WxT[64][hv*256 .. +256) -> swizzled smem ----
        {
            const uint4* gB = (const uint4*)(d_WxT + (size_t)bt*HH*NN);
            #pragma unroll
            for (int t = tid; t < 2048; t += 256) {
                int n = t >> 5, c = t & 31;
                uint4 v = gB[n*64 + hv*32 + c];
                *(uint4*)(smem + SB + n*512 + ((c ^ (n & 7)) << 4)) = v;
            }
        }
        // ---- phase A: P numerators fp16x2 (mask via register shuffle) ----
        #pragma unroll 1
        for (int qi = 0; qi < 16; qi++) {
            int q = w*16 + qi;
            float dq = __ldg(&d_adst[bt*NN + mtile*128 + q]);
            float mqf = fmaxf(0.0f, dq + sxmax);
            __half2 dq2 = __float2half2_rn(dq);
            __half2 mq2 = __float2half2_rn(mqf);
            float lsum = 0.0f;
            #pragma unroll
            for (int jt = 0; jt < 4; jt++) {
                __half2 sj2 = ((const __half2*)(smem + SASRC))[hv*128 + jt*32 + lane];
                __half2 t2 = __hadd2(dq2, sj2);
                __half2 l2 = __hmax2(t2, __hmul2(t2, c02));
                __half2 e2 = __hsub2(l2, mq2);
                uint32_t p;
                asm("ex2.approx.f16x2 %0, %1;" : "=r"(p) : "r"(*(uint32_t*)&e2));
                uint32_t wrd = __shfl_sync(0xffffffffu, mw[hv*4 + jt], qi + (lane & 16));
                int bit = (lane & 15)*2;
                uint32_t m32 = (((wrd >> bit) & 1u) ? 0x0000FFFFu : 0u)
                             | (((wrd >> bit) & 2u) ? 0xFFFF0000u : 0u);
                p &= m32;
                int kb = jt*128 + lane*4;
                *(uint32_t*)(smem + SP + q*512 + (kb ^ ((q & 7) << 4))) = p;
                __half2 hp = *(__half2*)&p;
                float2 pf = __half22float2(hp);
                lsum += pf.x + pf.y;
            }
            lpr[qi] += lsum;
        }
        __syncthreads();

        // ---- GEMM half: 16 k-steps of 16 ----
        const char* Pb = smem + SP;
        const char* Bb = smem + SB;
        #pragma unroll 2
        for (int ks = 0; ks < 16; ks++) {
            int kb = ks*32 + tc4;
            uint32_t a[2][4], b[4][2];
            #pragma unroll
            for (int mf = 0; mf < 2; mf++) {
                int r0 = mbase + mf*16 + tm, r1 = r0 + 8;
                uint32_t sw0 = (uint32_t)((r0 & 7) << 4);
                uint32_t sw1 = (uint32_t)((r1 & 7) << 4);
                a[mf][0] = *(const uint32_t*)(Pb + r0*512 + (kb ^ sw0));
                a[mf][1] = *(const uint32_t*)(Pb + r1*512 + (kb ^ sw1));
                a[mf][2] = *(const uint32_t*)(Pb + r0*512 + ((kb + 16) ^ sw0));
                a[mf][3] = *(const uint32_t*)(Pb + r1*512 + ((kb + 16) ^ sw1));
            }
            #pragma unroll
            for (int nf = 0; nf < 4; nf++) {
                int n = nbase + nf*8 + tm;
                uint32_t sw = (uint32_t)((n & 7) << 4);
                b[nf][0] = *(const uint32_t*)(Bb + n*512 + (kb ^ sw));
                b[nf][1] = *(const uint32_t*)(Bb + n*512 + ((kb + 16) ^ sw));
            }
            #pragma unroll
            for (int mf = 0; mf < 2; mf++)
                #pragma unroll
                for (int nf = 0; nf < 4; nf++)
                    mma16816(acc[mf][nf], a[mf], b[nf]);
        }
        __syncthreads();   // P/B consumed; safe to restage next half
    }

    // ---- row sums -> sL ----
    #pragma unroll
    for (int qi = 0; qi < 16; qi++) {
        float l = lpr[qi];
        #pragma unroll
        for (int o = 16; o > 0; o >>= 1) l += __shfl_xor_sync(0xffffffffu, l, o);
        if (lane == 0) sLf[w*16 + qi] = l;
    }
    __syncthreads();

    // ---- normalize + bias -> D (reuses P region) ----
    float* D = (float*)(smem + SP);
    #pragma unroll
    for (int mf = 0; mf < 2; mf++) {
        int r = mbase + mf*16 + tm;
        float inv0 = 1.0f / sLf[r];
        float inv8 = 1.0f / sLf[r + 8];
        #pragma unroll
        for (int nf = 0; nf < 4; nf++) {
            int n = nbase + nf*8 + (lane & 3)*2;
            float b0 = sBias[n], b1 = sBias[n + 1];
            *(float2*)&D[r*DSTRIDE + n]       = make_float2(acc[mf][nf][0]*inv0 + b0,
                                                            acc[mf][nf][1]*inv0 + b1);
            *(float2*)&D[(r + 8)*DSTRIDE + n] = make_float2(acc[mf][nf][2]*inv8 + b0,
                                                            acc[mf][nf][3]*inv8 + b1);
        }
    }
    __syncthreads();

    // ---- fused 64->12 GRU input-gate projection ----
    if (tid < 128) {
        int q = tid;
        float g[12];
        #pragma unroll
        for (int k = 0; k < 12; k++) g[k] = sBih[k];
        #pragma unroll 8
        for (int h = 0; h < 64; h += 2) {
            float2 ov = *(const float2*)&D[q*DSTRIDE + h];
            #pragma unroll
            for (int k = 0; k < 12; k++) {
                g[k] = fmaf(sWih[k*64 + h], ov.x, g[k]);
                g[k] = fmaf(sWih[k*64 + h + 1], ov.y, g[k]);
            }
        }
        float* gp = d_gates + ((size_t)bt*NN + mtile*128 + q)*12;
        *(float4*)(gp + 0) = make_float4(g[0], g[1], g[2],  g[3]);
        *(float4*)(gp + 4) = make_float4(g[4], g[5], g[6],  g[7]);
        *(float4*)(gp + 8) = make_float4(g[8], g[9], g[10], g[11]);
    }
}

// ===== K3: fused GRU recurrence + Conv2d(8->12,3x3) + Linear(4->2) ==============
__device__ __forceinline__ float sigm(float v) { return 1.0f / (1.0f + __expf(-v)); }

__global__ void __launch_bounds__(256)
k_tail(const float* __restrict__ W_hh, const float* __restrict__ b_hh,
       const float* __restrict__ conv_W, const float* __restrict__ conv_b,
       const float* __restrict__ out_W,  const float* __restrict__ out_b,
       float* __restrict__ out)
{
    __shared__ float sg[8][130][4];     // [t][nl][f], nl = n - (nt*128 - 1)
    __shared__ float sWhh[48], sbhh[12];
    __shared__ float sCW[864], sOW[8], sOB[2], sCB[12];

    int b  = blockIdx.x >> 2;
    int nt = blockIdx.x & 3;
    int tid = threadIdx.x;

    for (int i = tid; i < 864; i += 256) sCW[i] = conv_W[i];
    if (tid < 48) sWhh[tid] = W_hh[tid];
    if (tid < 12) sbhh[tid] = b_hh[tid];
    if (tid < 8)  sOW[tid]  = out_W[tid];
    if (tid < 2)  sOB[tid]  = out_b[tid];
    if (tid >= 16 && tid < 28) sCB[tid - 16] = conv_b[tid - 16];
    for (int i = tid; i < 8*130*4; i += 256) ((float*)sg)[i] = 0.0f;
    __syncthreads();

    // ---- GRU: threads 0..129, sequence n = nt*128 - 1 + tid ----
    if (tid < 130) {
        int n = nt*128 - 1 + tid;
        if (n >= 0 && n < 512) {
            const float* gbase = d_gates + ((size_t)b*4096 + (size_t)n*8)*12;
            float4 c0 = *(const float4*)(gbase + 0);
            float4 c1 = *(const float4*)(gbase + 4);
            float4 c2 = *(const float4*)(gbase + 8);
            float h0 = 0.f, h1 = 0.f, h2 = 0.f, h3 = 0.f;
            #pragma unroll
            for (int s = 0; s < 8; s++) {
                float4 n0, n1, n2;
                if (s < 7) {
                    const float* gnext = gbase + (s + 1)*12;
                    n0 = *(const float4*)(gnext + 0);
                    n1 = *(const float4*)(gnext + 4);
                    n2 = *(const float4*)(gnext + 8);
                }
                float gh[12];
                #pragma unroll
                for (int k = 0; k < 12; k++)
                    gh[k] = sbhh[k] + sWhh[k*4+0]*h0 + sWhh[k*4+1]*h1
                                    + sWhh[k*4+2]*h2 + sWhh[k*4+3]*h3;
                float r0 = sigm(c0.x + gh[0]), r1 = sigm(c0.y + gh[1]);
                float r2 = sigm(c0.z + gh[2]), r3 = sigm(c0.w + gh[3]);
                float z0 = sigm(c1.x + gh[4]), z1 = sigm(c1.y + gh[5]);
                float z2 = sigm(c1.z + gh[6]), z3 = sigm(c1.w + gh[7]);
                float cc0 = tanhf(c2.x + r0*gh[8]),  cc1 = tanhf(c2.y + r1*gh[9]);
                float cc2 = tanhf(c2.z + r2*gh[10]), cc3 = tanhf(c2.w + r3*gh[11]);
                h0 = (1.0f - z0)*cc0 + z0*h0;
                h1 = (1.0f - z1)*cc1 + z1*h1;
                h2 = (1.0f - z2)*cc2 + z2*h2;
                h3 = (1.0f - z3)*cc3 + z3*h3;
                sg[s][tid][0] = h0; sg[s][tid][1] = h1;
                sg[s][tid][2] = h2; sg[s][tid][3] = h3;
                c0 = n0; c1 = n1; c2 = n2;
            }
        }
    }
    __syncthreads();

    // ---- Conv 3x3 over n (channels = t) + Linear(4->2), 6 outputs/thread ----
    #pragma unroll
    for (int k6 = 0; k6 < 6; k6++) {
        int oidx = tid + k6*256;          // 0..1535 = (co, nloc)
        int co   = oidx >> 7;
        int nloc = oidx & 127;
        float y0, y1, y2, y3;
        y0 = y1 = y2 = y3 = sCB[co];
        #pragma unroll
        for (int ci = 0; ci < 8; ci++) {
            #pragma unroll
            for (int kh = 0; kh < 3; kh++) {
                const float4 v = *(const float4*)&sg[ci][nloc + kh][0];
                const float* wr = &sCW[(co*8 + ci)*9 + kh*3];
                float w0 = wr[0], w1 = wr[1], w2 = wr[2];
                y0 += v.x*w1 + v.y*w2;
                y1 += v.x*w0 + v.y*w1 + v.z*w2;
                y2 += v.y*w0 + v.z*w1 + v.w*w2;
                y3 += v.z*w0 + v.w*w1;
            }
        }
        float o0 = sOB[0] + y0*sOW[0] + y1*sOW[1] + y2*sOW[2] + y3*sOW[3];
        float o1 = sOB[1] + y0*sOW[4] + y1*sOW[5] + y2*sOW[6] + y3*sOW[7];
        int n = nt*128 + nloc;
        *(float2*)&out[(size_t)((b*12 + co)*512 + n)*2] = make_float2(o0, o1);
    }
}

// ================================ launch =========================================
extern "C" void kernel_launch(void* const* d_in, const int* in_sizes, int n_in,
                              void* d_out, int out_size)
{
    const float* x        = (const float*)d_in[0];
    const float* adj      = (const float*)d_in[1];
    const float* gat_W    = (const float*)d_in[2];
    const float* att_src  = (const float*)d_in[3];
    const float* att_dst  = (const float*)d_in[4];
    const float* gat_bias = (const float*)d_in[5];
    const float* W_ih     = (const float*)d_in[6];
    const float* W_hh     = (const float*)d_in[7];
    const float* b_ih     = (const float*)d_in[8];
    const float* b_hh     = (const float*)d_in[9];
    const float* conv_W   = (const float*)d_in[10];
    const float* conv_b   = (const float*)d_in[11];
    const float* out_W    = (const float*)d_in[12];
    const float* out_b    = (const float*)d_in[13];
    float* out = (float*)d_out;

    cudaFuncSetAttribute(k_attn, cudaFuncAttributeMaxDynamicSharedMemorySize, SME_TOTAL);

    k_proj<<<BTN, 256>>>(x, gat_W, att_src, att_dst);
    k_attn<<<BTN*4, 256, SME_TOTAL>>>(adj, gat_bias, W_ih, b_ih);
    k_tail<<<BB*4, 256>>>(W_hh, b_hh, conv_W, conv_b, out_W, out_b, out);
}

// round 7
// speedup vs baseline: 1.0744x; 1.0744x over previous
#include <cuda_runtime.h>
#include <cuda_fp16.h>
#include <math.h>
#include <cstdint>

#define BB 32
#define TT 8
#define NN 512
#define FF 4
#define HH 64
#define ROWS (BB*TT*NN)
#define BTN  (BB*TT)
#define LOG2E 1.4426950408889634f

// ---------------- scratch (static device globals; no allocation) ----------------
__device__ float d_asrc[ROWS];               // pre-scaled by log2(e)
__device__ float d_adst[ROWS];               // pre-scaled by log2(e)
__device__ float d_gates[(size_t)ROWS*12];

// ============ K1: a_src/a_dst only (log2-scaled) =================================
__global__ void k_proj(const float* __restrict__ x, const float* __restrict__ gat_W,
                       const float* __restrict__ att_src, const float* __restrict__ att_dst)
{
    __shared__ float sW[256];
    __shared__ float su[4], sv[4];
    int bt = blockIdx.x, tid = threadIdx.x;
    int w = tid >> 5, lane = tid & 31;

    if (tid < 256) sW[tid] = gat_W[tid];
    __syncthreads();

    if (w == 0) {
        float as0 = __ldg(&att_src[lane]), as1 = __ldg(&att_src[32 + lane]);
        float ad0 = __ldg(&att_dst[lane]), ad1 = __ldg(&att_dst[32 + lane]);
        #pragma unroll
        for (int f = 0; f < 4; f++) {
            float uu = sW[f*64 + lane]*as0 + sW[f*64 + 32 + lane]*as1;
            float vv = sW[f*64 + lane]*ad0 + sW[f*64 + 32 + lane]*ad1;
            #pragma unroll
            for (int o = 16; o > 0; o >>= 1) {
                uu += __shfl_xor_sync(0xffffffffu, uu, o);
                vv += __shfl_xor_sync(0xffffffffu, vv, o);
            }
            if (lane == 0) { su[f] = uu*LOG2E; sv[f] = vv*LOG2E; }
        }
    }
    __syncthreads();

    const float4* gx = (const float4*)(x + (size_t)bt*NN*FF);
    #pragma unroll
    for (int r = 0; r < 2; r++) {
        int j = tid + r*256;
        float4 a = gx[j];
        d_asrc[bt*NN + j] = a.x*su[0] + a.y*su[1] + a.z*su[2] + a.w*su[3];
        d_adst[bt*NN + j] = a.x*sv[0] + a.y*sv[1] + a.z*sv[2] + a.w*sv[3];
    }
}

// ===== K2: in-CTA Wx + smem mask(per-half) + fp16x2 softmax + HMMA + gates ======
#define SP     0          /* P half tile: 128 x 512B fp16 XOR-swizzled; D reuses */
#define SB     65536      /* B half tile: 64 x 512B fp16 XOR-swizzled */
#define SX     98304      /* x tile fp16: 512 j x 4 f = 4096B */
#define SMASK  102400     /* per-half mask: 128 x 8 words = 4096B */
#define SASRC  106496     /* 512 half = 1024 */
#define SWIH   107520     /* 768 f32 = 3072 */
#define SBIAS  110592     /* 64 f32 */
#define SBIH   110848     /* 16 f32 */
#define SL     110912     /* 128 f32 */
#define SW     111424     /* gat_W 256 f32 = 1024 */
#define SME_TOTAL 112448
#define DSTRIDE 66

__device__ __forceinline__ void mma16816(float* d, const uint32_t* a, const uint32_t* b)
{
    asm volatile("mma.sync.aligned.m16n8k16.row.col.f32.f16.f16.f32 "
        "{%0,%1,%2,%3}, {%4,%5,%6,%7}, {%8,%9}, {%0,%1,%2,%3};"
        : "+f"(d[0]), "+f"(d[1]), "+f"(d[2]), "+f"(d[3])
        : "r"(a[0]), "r"(a[1]), "r"(a[2]), "r"(a[3]), "r"(b[0]), "r"(b[1]));
}

__global__ void __launch_bounds__(256, 2)
k_attn(const float* __restrict__ x, const float* __restrict__ adj,
       const float* __restrict__ gat_W, const float* __restrict__ gat_bias,
       const float* __restrict__ W_ih, const float* __restrict__ b_ih)
{
    extern __shared__ char smem[];
    float*    sWih  = (float*)(smem + SWIH);
    float*    sBias = (float*)(smem + SBIAS);
    float*    sBih  = (float*)(smem + SBIH);
    float*    sLf   = (float*)(smem + SL);
    float*    sWg   = (float*)(smem + SW);
    uint32_t* sMask = (uint32_t*)(smem + SMASK);
    __half2*  sx2   = (__half2*)(smem + SX);

    int bt    = blockIdx.x >> 2;
    int mtile = blockIdx.x & 3;
    int tid   = threadIdx.x;
    int w     = tid >> 5, lane = tid & 31;

    // ---- stage small things + x tile (fp16) ----
    for (int i = tid; i < 768; i += 256) sWih[i] = __ldg(&W_ih[i]);
    if (tid < 64)  sBias[tid] = __ldg(&gat_bias[tid]);
    if (tid < 12)  sBih[tid]  = __ldg(&b_ih[tid]);
    if (tid < 256) sWg[tid]   = __ldg(&gat_W[tid]);
    {
        const float4* gx = (const float4*)(x + (size_t)bt*NN*FF);
        #pragma unroll
        for (int r = 0; r < 2; r++) {
            int j = tid + r*256;
            float4 v = gx[j];
            sx2[j*2]     = __floats2half2_rn(v.x, v.y);
            sx2[j*2 + 1] = __floats2half2_rn(v.z, v.w);
        }
    }
    if (tid < 256) {
        float2 v = *(const float2*)&d_asrc[bt*NN + tid*2];
        ((__half2*)(smem + SASRC))[tid] = __floats2half2_rn(v.x, v.y);
    }
    __syncthreads();

    // ---- warp-uniform max of (log2-scaled) a_src ----
    float sxmax;
    {
        const __half2* sa2 = (const __half2*)(smem + SASRC);
        __half2 mx = __floats2half2_rn(-60000.f, -60000.f);
        #pragma unroll
        for (int k = 0; k < 8; k++) mx = __hmax2(mx, sa2[lane*8 + k]);
        float m = fmaxf(__low2float(mx), __high2float(mx));
        #pragma unroll
        for (int o = 16; o > 0; o >>= 1) m = fmaxf(m, __shfl_xor_sync(0xffffffffu, m, o));
        sxmax = m;
    }

    const __half2 c02 = __floats2half2_rn(0.2f, 0.2f);
    float lpr[16];
    #pragma unroll
    for (int qi = 0; qi < 16; qi++) lpr[qi] = 0.0f;

    float acc[2][4][4];
    #pragma unroll
    for (int mf = 0; mf < 2; mf++)
        #pragma unroll
        for (int nf = 0; nf < 4; nf++)
            #pragma unroll
            for (int r = 0; r < 4; r++) acc[mf][nf][r] = 0.0f;

    int mg = w & 3, ng = w >> 2;
    int mbase = mg*32, nbase = ng*32;
    int tm = lane >> 2;
    int tc4 = (lane & 3)*4;

    const float* adjbt = adj + (size_t)bt*NN*NN;

    #pragma unroll 1
    for (int hv = 0; hv < 2; hv++) {
        // ---- compute B half in-CTA: B[h][jl] = fp16(Wx), XOR-swizzled ----
        {
            int h  = tid & 63;
            int jc = tid >> 6;               // 0..3, chunk of 64 j
            float w0 = sWg[h], w1 = sWg[64 + h], w2 = sWg[128 + h], w3 = sWg[192 + h];
            char* brow = smem + SB + h*512;
            uint32_t sw = (uint32_t)((h & 7) << 4);
            #pragma unroll 8
            for (int k = 0; k < 64; k += 2) {
                int jl = jc*64 + k;
                int jg = hv*256 + jl;
                float2 a0 = __half22float2(sx2[jg*2]);
                float2 a1 = __half22float2(sx2[jg*2 + 1]);
                float2 b0 = __half22float2(sx2[jg*2 + 2]);
                float2 b1 = __half22float2(sx2[jg*2 + 3]);
                float wx0 = a0.x*w0 + a0.y*w1 + a1.x*w2 + a1.y*w3;
                float wx1 = b0.x*w0 + b0.y*w1 + b1.x*w2 + b1.y*w3;
                *(__half2*)(brow + ((uint32_t)(jl*2) ^ sw)) = __floats2half2_rn(wx0, wx1);
            }
        }
        // ---- build mask half: rows 128 x 8 words ----
        #pragma unroll 1
        for (int t8 = 0; t8 < 4; t8++) {
            int t = w*4 + t8;                 // 0..31
            int itile = t >> 3;               // 0..3
            int jtl   = t & 7;                // 0..7
            int jtb   = hv*8 + jtl;
            int ig = mtile*128 + itile*32 + lane;
            const float* col = adjbt + (size_t)(jtb*32)*NN + ig;
            uint32_t word = 0;
            #pragma unroll
            for (int jl = 0; jl < 32; jl++)
                word |= (__ldg(&col[(size_t)jl*NN]) != 0.0f ? 1u : 0u) << jl;
            if ((ig >> 5) == jtb) word |= 1u << (ig & 31);
            sMask[(itile*32 + lane)*8 + jtl] = word;
        }
        __syncthreads();

        // ---- phase A: P numerators fp16x2 ----
        #pragma unroll 1
        for (int qi = 0; qi < 16; qi++) {
            int q = w*16 + qi;
            float dq = __ldg(&d_adst[bt*NN + mtile*128 + q]);
            float mqf = fmaxf(0.0f, dq + sxmax);
            __half2 dq2 = __float2half2_rn(dq);
            __half2 mq2 = __float2half2_rn(mqf);
            float lsum = 0.0f;
            #pragma unroll
            for (int jt = 0; jt < 4; jt++) {
                __half2 sj2 = ((const __half2*)(smem + SASRC))[hv*128 + jt*32 + lane];
                __half2 t2 = __hadd2(dq2, sj2);
                __half2 l2 = __hmax2(t2, __hmul2(t2, c02));
                __half2 e2 = __hsub2(l2, mq2);
                uint32_t p;
                asm("ex2.approx.f16x2 %0, %1;" : "=r"(p) : "r"(*(uint32_t*)&e2));
                uint32_t wrd = sMask[q*8 + jt*2 + (lane >> 4)];
                int bit = (lane & 15)*2;
                uint32_t m32 = (((wrd >> bit) & 1u) ? 0x0000FFFFu : 0u)
                             | (((wrd >> bit) & 2u) ? 0xFFFF0000u : 0u);
                p &= m32;
                int kb = jt*128 + lane*4;
                *(uint32_t*)(smem + SP + q*512 + (kb ^ ((q & 7) << 4))) = p;
                __half2 hp = *(__half2*)&p;
                float2 pf = __half22float2(hp);
                lsum += pf.x + pf.y;
            }
            lpr[qi] += lsum;
        }
        __syncthreads();

        // ---- GEMM half: 16 k-steps of 16 ----
        const char* Pb = smem + SP;
        const char* Bb = smem + SB;
        #pragma unroll 2
        for (int ks = 0; ks < 16; ks++) {
            int kb = ks*32 + tc4;
            uint32_t a[2][4], b[4][2];
            #pragma unroll
            for (int mf = 0; mf < 2; mf++) {
                int r0 = mbase + mf*16 + tm, r1 = r0 + 8;
                uint32_t sw0 = (uint32_t)((r0 & 7) << 4);
                uint32_t sw1 = (uint32_t)((r1 & 7) << 4);
                a[mf][0] = *(const uint32_t*)(Pb + r0*512 + (kb ^ sw0));
                a[mf][1] = *(const uint32_t*)(Pb + r1*512 + (kb ^ sw1));
                a[mf][2] = *(const uint32_t*)(Pb + r0*512 + ((kb + 16) ^ sw0));
                a[mf][3] = *(const uint32_t*)(Pb + r1*512 + ((kb + 16) ^ sw1));
            }
            #pragma unroll
            for (int nf = 0; nf < 4; nf++) {
                int n = nbase + nf*8 + tm;
                uint32_t sw = (uint32_t)((n & 7) << 4);
                b[nf][0] = *(const uint32_t*)(Bb + n*512 + (kb ^ sw));
                b[nf][1] = *(const uint32_t*)(Bb + n*512 + ((kb + 16) ^ sw));
            }
            #pragma unroll
            for (int mf = 0; mf < 2; mf++)
                #pragma unroll
                for (int nf = 0; nf < 4; nf++)
                    mma16816(acc[mf][nf], a[mf], b[nf]);
        }
        __syncthreads();   // P/B/mask consumed; safe to restage next half
    }

    // ---- row sums -> sL ----
    #pragma unroll
    for (int qi = 0; qi < 16; qi++) {
        float l = lpr[qi];
        #pragma unroll
        for (int o = 16; o > 0; o >>= 1) l += __shfl_xor_sync(0xffffffffu, l, o);
        if (lane == 0) sLf[w*16 + qi] = l;
    }
    __syncthreads();

    // ---- normalize + bias -> D (reuses P region) ----
    float* D = (float*)(smem + SP);
    #pragma unroll
    for (int mf = 0; mf < 2; mf++) {
        int r = mbase + mf*16 + tm;
        float inv0 = 1.0f / sLf[r];
        float inv8 = 1.0f / sLf[r + 8];
        #pragma unroll
        for (int nf = 0; nf < 4; nf++) {
            int n = nbase + nf*8 + (lane & 3)*2;
            float b0 = sBias[n], b1 = sBias[n + 1];
            *(float2*)&D[r*DSTRIDE + n]       = make_float2(acc[mf][nf][0]*inv0 + b0,
                                                            acc[mf][nf][1]*inv0 + b1);
            *(float2*)&D[(r + 8)*DSTRIDE + n] = make_float2(acc[mf][nf][2]*inv8 + b0,
                                                            acc[mf][nf][3]*inv8 + b1);
        }
    }
    __syncthreads();

    // ---- fused 64->12 GRU input-gate projection ----
    if (tid < 128) {
        int q = tid;
        float g[12];
        #pragma unroll
        for (int k = 0; k < 12; k++) g[k] = sBih[k];
        #pragma unroll 8
        for (int h = 0; h < 64; h += 2) {
            float2 ov = *(const float2*)&D[q*DSTRIDE + h];
            #pragma unroll
            for (int k = 0; k < 12; k++) {
                g[k] = fmaf(sWih[k*64 + h], ov.x, g[k]);
                g[k] = fmaf(sWih[k*64 + h + 1], ov.y, g[k]);
            }
        }
        float* gp = d_gates + ((size_t)bt*NN + mtile*128 + q)*12;
        *(float4*)(gp + 0) = make_float4(g[0], g[1], g[2],  g[3]);
        *(float4*)(gp + 4) = make_float4(g[4], g[5], g[6],  g[7]);
        *(float4*)(gp + 8) = make_float4(g[8], g[9], g[10], g[11]);
    }
}

// ===== K3: fused GRU recurrence + Conv2d(8->12,3x3) + Linear(4->2) ==============
__device__ __forceinline__ float sigm(float v) { return 1.0f / (1.0f + __expf(-v)); }

__global__ void __launch_bounds__(256)
k_tail(const float* __restrict__ W_hh, const float* __restrict__ b_hh,
       const float* __restrict__ conv_W, const float* __restrict__ conv_b,
       const float* __restrict__ out_W,  const float* __restrict__ out_b,
       float* __restrict__ out)
{
    __shared__ float sg[8][130][4];
    __shared__ float sWhh[48], sbhh[12];
    __shared__ float sCW[864], sOW[8], sOB[2], sCB[12];

    int b  = blockIdx.x >> 2;
    int nt = blockIdx.x & 3;
    int tid = threadIdx.x;

    for (int i = tid; i < 864; i += 256) sCW[i] = conv_W[i];
    if (tid < 48) sWhh[tid] = W_hh[tid];
    if (tid < 12) sbhh[tid] = b_hh[tid];
    if (tid < 8)  sOW[tid]  = out_W[tid];
    if (tid < 2)  sOB[tid]  = out_b[tid];
    if (tid >= 16 && tid < 28) sCB[tid - 16] = conv_b[tid - 16];
    for (int i = tid; i < 8*130*4; i += 256) ((float*)sg)[i] = 0.0f;
    __syncthreads();

    if (tid < 130) {
        int n = nt*128 - 1 + tid;
        if (n >= 0 && n < 512) {
            const float* gbase = d_gates + ((size_t)b*4096 + (size_t)n*8)*12;
            float4 c0 = *(const float4*)(gbase + 0);
            float4 c1 = *(const float4*)(gbase + 4);
            float4 c2 = *(const float4*)(gbase + 8);
            float h0 = 0.f, h1 = 0.f, h2 = 0.f, h3 = 0.f;
            #pragma unroll
            for (int s = 0; s < 8; s++) {
                float4 n0, n1, n2;
                if (s < 7) {
                    const float* gnext = gbase + (s + 1)*12;
                    n0 = *(const float4*)(gnext + 0);
                    n1 = *(const float4*)(gnext + 4);
                    n2 = *(const float4*)(gnext + 8);
                }
                float gh[12];
                #pragma unroll
                for (int k = 0; k < 12; k++)
                    gh[k] = sbhh[k] + sWhh[k*4+0]*h0 + sWhh[k*4+1]*h1
                                    + sWhh[k*4+2]*h2 + sWhh[k*4+3]*h3;
                float r0 = sigm(c0.x + gh[0]), r1 = sigm(c0.y + gh[1]);
                float r2 = sigm(c0.z + gh[2]), r3 = sigm(c0.w + gh[3]);
                float z0 = sigm(c1.x + gh[4]), z1 = sigm(c1.y + gh[5]);
                float z2 = sigm(c1.z + gh[6]), z3 = sigm(c1.w + gh[7]);
                float cc0 = tanhf(c2.x + r0*gh[8]),  cc1 = tanhf(c2.y + r1*gh[9]);
                float cc2 = tanhf(c2.z + r2*gh[10]), cc3 = tanhf(c2.w + r3*gh[11]);
                h0 = (1.0f - z0)*cc0 + z0*h0;
                h1 = (1.0f - z1)*cc1 + z1*h1;
                h2 = (1.0f - z2)*cc2 + z2*h2;
                h3 = (1.0f - z3)*cc3 + z3*h3;
                sg[s][tid][0] = h0; sg[s][tid][1] = h1;
                sg[s][tid][2] = h2; sg[s][tid][3] = h3;
                c0 = n0; c1 = n1; c2 = n2;
            }
        }
    }
    __syncthreads();

    #pragma unroll
    for (int k6 = 0; k6 < 6; k6++) {
        int oidx = tid + k6*256;
        int co   = oidx >> 7;
        int nloc = oidx & 127;
        float y0, y1, y2, y3;
        y0 = y1 = y2 = y3 = sCB[co];
        #pragma unroll
        for (int ci = 0; ci < 8; ci++) {
            #pragma unroll
            for (int kh = 0; kh < 3; kh++) {
                const float4 v = *(const float4*)&sg[ci][nloc + kh][0];
                const float* wr = &sCW[(co*8 + ci)*9 + kh*3];
                float w0 = wr[0], w1 = wr[1], w2 = wr[2];
                y0 += v.x*w1 + v.y*w2;
                y1 += v.x*w0 + v.y*w1 + v.z*w2;
                y2 += v.y*w0 + v.z*w1 + v.w*w2;
                y3 += v.z*w0 + v.w*w1;
            }
        }
        float o0 = sOB[0] + y0*sOW[0] + y1*sOW[1] + y2*sOW[2] + y3*sOW[3];
        float o1 = sOB[1] + y0*sOW[4] + y1*sOW[5] + y2*sOW[6] + y3*sOW[7];
        int n = nt*128 + nloc;
        *(float2*)&out[(size_t)((b*12 + co)*512 + n)*2] = make_float2(o0, o1);
    }
}

// ================================ launch =========================================
extern "C" void kernel_launch(void* const* d_in, const int* in_sizes, int n_in,
                              void* d_out, int out_size)
{
    const float* x        = (const float*)d_in[0];
    const float* adj      = (const float*)d_in[1];
    const float* gat_W    = (const float*)d_in[2];
    const float* att_src  = (const float*)d_in[3];
    const float* att_dst  = (const float*)d_in[4];
    const float* gat_bias = (const float*)d_in[5];
    const float* W_ih     = (const float*)d_in[6];
    const float* W_hh     = (const float*)d_in[7];
    const float* b_ih     = (const float*)d_in[8];
    const float* b_hh     = (const float*)d_in[9];
    const float* conv_W   = (const float*)d_in[10];
    const float* conv_b   = (const float*)d_in[11];
    const float* out_W    = (const float*)d_in[12];
    const float* out_b    = (const float*)d_in[13];
    float* out = (float*)d_out;

    cudaFuncSetAttribute(k_attn, cudaFuncAttributeMaxDynamicSharedMemorySize, SME_TOTAL);

    k_proj<<<BTN, 256>>>(x, gat_W, att_src, att_dst);
    k_attn<<<BTN*4, 256, SME_TOTAL>>>(x, adj, gat_W, gat_bias, W_ih, b_ih);
    k_tail<<<BB*4, 256>>>(W_hh, b_hh, conv_W, conv_b, out_W, out_b, out);
}

// round 12
// speedup vs baseline: 1.1034x; 1.0269x over previous
#include <cuda_runtime.h>
#include <cuda_fp16.h>
#include <math.h>
#include <cstdint>

#define BB 32
#define TT 8
#define NN 512
#define FF 4
#define HH 64
#define ROWS (BB*TT*NN)
#define BTN  (BB*TT)
#define LOG2E 1.4426950408889634f

// ---------------- scratch (static device globals; no allocation) ----------------
__device__ float d_asrc[ROWS];               // pre-scaled by log2(e)
__device__ float d_adst[ROWS];               // pre-scaled by log2(e)
__device__ float d_gates[(size_t)ROWS*12];

// ============ K1: a_src/a_dst only (log2-scaled) =================================
__global__ void k_proj(const float* __restrict__ x, const float* __restrict__ gat_W,
                       const float* __restrict__ att_src, const float* __restrict__ att_dst)
{
    __shared__ float sW[256];
    __shared__ float su[4], sv[4];
    int bt = blockIdx.x, tid = threadIdx.x;
    int w = tid >> 5, lane = tid & 31;

    if (tid < 256) sW[tid] = gat_W[tid];
    __syncthreads();

    if (w == 0) {
        float as0 = __ldg(&att_src[lane]), as1 = __ldg(&att_src[32 + lane]);
        float ad0 = __ldg(&att_dst[lane]), ad1 = __ldg(&att_dst[32 + lane]);
        #pragma unroll
        for (int f = 0; f < 4; f++) {
            float uu = sW[f*64 + lane]*as0 + sW[f*64 + 32 + lane]*as1;
            float vv = sW[f*64 + lane]*ad0 + sW[f*64 + 32 + lane]*ad1;
            #pragma unroll
            for (int o = 16; o > 0; o >>= 1) {
                uu += __shfl_xor_sync(0xffffffffu, uu, o);
                vv += __shfl_xor_sync(0xffffffffu, vv, o);
            }
            if (lane == 0) { su[f] = uu*LOG2E; sv[f] = vv*LOG2E; }
        }
    }
    __syncthreads();

    const float4* gx = (const float4*)(x + (size_t)bt*NN*FF);
    #pragma unroll
    for (int r = 0; r < 2; r++) {
        int j = tid + r*256;
        float4 a = gx[j];
        d_asrc[bt*NN + j] = a.x*su[0] + a.y*su[1] + a.z*su[2] + a.w*su[3];
        d_adst[bt*NN + j] = a.x*sv[0] + a.y*sv[1] + a.z*sv[2] + a.w*sv[3];
    }
}

// ===== K2: quarter-K tiles, occ=3: Wx + mask + fp16x2 softmax + HMMA + gates ====
#define SP     0          /* P quarter: 128 q x 256B (128 j fp16, XOR swz); D reuses */
#define SB     32768      /* B quarter: 64 n x 256B */
#define SX     49152      /* x tile fp16: 512 x 4 = 4096B */
#define SMASK  53248      /* quarter mask: 128 x 4 words = 2048B */
#define SASRC  55296      /* 512 half = 1024 */
#define SWIH   56320      /* 768 f32 = 3072 */
#define SBIAS  59392      /* 64 f32 */
#define SBIH   59648      /* 16 f32 */
#define SL     59712      /* 128 f32 */
#define SW     60224      /* gat_W 256 f32 = 1024 */
#define SME_TOTAL 61248
#define DSTRIDE 66

__device__ __forceinline__ void mma16816(float* d, const uint32_t* a, const uint32_t* b)
{
    asm volatile("mma.sync.aligned.m16n8k16.row.col.f32.f16.f16.f32 "
        "{%0,%1,%2,%3}, {%4,%5,%6,%7}, {%8,%9}, {%0,%1,%2,%3};"
        : "+f"(d[0]), "+f"(d[1]), "+f"(d[2]), "+f"(d[3])
        : "r"(a[0]), "r"(a[1]), "r"(a[2]), "r"(a[3]), "r"(b[0]), "r"(b[1]));
}

__global__ void __launch_bounds__(256, 3)
k_attn(const float* __restrict__ x, const float* __restrict__ adj,
       const float* __restrict__ gat_W, const float* __restrict__ gat_bias,
       const float* __restrict__ W_ih, const float* __restrict__ b_ih)
{
    extern __shared__ char smem[];
    float*    sWih  = (float*)(smem + SWIH);
    float*    sBias = (float*)(smem + SBIAS);
    float*    sBih  = (float*)(smem + SBIH);
    float*    sLf   = (float*)(smem + SL);
    float*    sWg   = (float*)(smem + SW);
    uint32_t* sMask = (uint32_t*)(smem + SMASK);
    __half2*  sx2   = (__half2*)(smem + SX);

    int bt    = blockIdx.x >> 2;
    int mtile = blockIdx.x & 3;
    int tid   = threadIdx.x;
    int w     = tid >> 5, lane = tid & 31;

    // ---- stage small things + x tile (fp16) ----
    for (int i = tid; i < 768; i += 256) sWih[i] = __ldg(&W_ih[i]);
    if (tid < 64)  sBias[tid] = __ldg(&gat_bias[tid]);
    if (tid < 12)  sBih[tid]  = __ldg(&b_ih[tid]);
    if (tid < 128) sLf[tid]   = 0.0f;
    if (tid < 256) sWg[tid]   = __ldg(&gat_W[tid]);
    {
        const float4* gx = (const float4*)(x + (size_t)bt*NN*FF);
        #pragma unroll
        for (int r = 0; r < 2; r++) {
            int j = tid + r*256;
            float4 v = gx[j];
            sx2[j*2]     = __floats2half2_rn(v.x, v.y);
            sx2[j*2 + 1] = __floats2half2_rn(v.z, v.w);
        }
    }
    if (tid < 256) {
        float2 v = *(const float2*)&d_asrc[bt*NN + tid*2];
        ((__half2*)(smem + SASRC))[tid] = __floats2half2_rn(v.x, v.y);
    }
    __syncthreads();

    // ---- warp-uniform max of (log2-scaled) a_src ----
    float sxmax;
    {
        const __half2* sa2 = (const __half2*)(smem + SASRC);
        __half2 mx = __floats2half2_rn(-60000.f, -60000.f);
        #pragma unroll
        for (int k = 0; k < 8; k++) mx = __hmax2(mx, sa2[lane*8 + k]);
        float m = fmaxf(__low2float(mx), __high2float(mx));
        #pragma unroll
        for (int o = 16; o > 0; o >>= 1) m = fmaxf(m, __shfl_xor_sync(0xffffffffu, m, o));
        sxmax = m;
    }

    const __half2 c02 = __floats2half2_rn(0.2f, 0.2f);

    float acc[2][4][4];
    #pragma unroll
    for (int mf = 0; mf < 2; mf++)
        #pragma unroll
        for (int nf = 0; nf < 4; nf++)
            #pragma unroll
            for (int r = 0; r < 4; r++) acc[mf][nf][r] = 0.0f;

    int mg = w & 3, ng = w >> 2;
    int mbase = mg*32, nbase = ng*32;
    int tm = lane >> 2;
    int tc4 = (lane & 3)*4;

    const float* adjbt = adj + (size_t)bt*NN*NN;

    #pragma unroll 1
    for (int hq = 0; hq < 4; hq++) {
        // ---- compute B quarter in-CTA: B[h][jl] = fp16(Wx), XOR-swizzled ----
        {
            int h  = tid & 63;
            int jc = tid >> 6;               // 0..3, chunk of 32 j
            float w0 = sWg[h], w1 = sWg[64 + h], w2 = sWg[128 + h], w3 = sWg[192 + h];
            char* brow = smem + SB + h*256;
            uint32_t sw = (uint32_t)((h & 7) << 4);
            #pragma unroll 8
            for (int k = 0; k < 32; k += 2) {
                int jl = jc*32 + k;
                int jg = hq*128 + jl;
                float2 a0 = __half22float2(sx2[jg*2]);
                float2 a1 = __half22float2(sx2[jg*2 + 1]);
                float2 b0 = __half22float2(sx2[jg*2 + 2]);
                float2 b1 = __half22float2(sx2[jg*2 + 3]);
                float wx0 = a0.x*w0 + a0.y*w1 + a1.x*w2 + a1.y*w3;
                float wx1 = b0.x*w0 + b0.y*w1 + b1.x*w2 + b1.y*w3;
                *(__half2*)(brow + ((uint32_t)(jl*2) ^ sw)) = __floats2half2_rn(wx0, wx1);
            }
        }
        // ---- build mask quarter: 128 rows x 4 words ----
        #pragma unroll 1
        for (int t8 = 0; t8 < 2; t8++) {
            int t = w*2 + t8;                 // 0..15
            int itile = t >> 2;               // 0..3
            int jtl   = t & 3;                // 0..3
            int jtb   = hq*4 + jtl;
            int ig = mtile*128 + itile*32 + lane;
            const float* col = adjbt + (size_t)(jtb*32)*NN + ig;
            uint32_t word = 0;
            #pragma unroll
            for (int jl = 0; jl < 32; jl++)
                word |= (__ldg(&col[(size_t)jl*NN]) != 0.0f ? 1u : 0u) << jl;
            if ((ig >> 5) == jtb) word |= 1u << (ig & 31);
            sMask[(itile*32 + lane)*4 + jtl] = word;
        }
        __syncthreads();

        // ---- phase A: P quarter numerators fp16x2 ----
        #pragma unroll 1
        for (int qi = 0; qi < 16; qi++) {
            int q = w*16 + qi;
            float dq = __ldg(&d_adst[bt*NN + mtile*128 + q]);
            float mqf = fmaxf(0.0f, dq + sxmax);
            __half2 dq2 = __float2half2_rn(dq);
            __half2 mq2 = __float2half2_rn(mqf);
            float lsum = 0.0f;
            #pragma unroll
            for (int jt = 0; jt < 2; jt++) {
                __half2 sj2 = ((const __half2*)(smem + SASRC))[hq*64 + jt*32 + lane];
                __half2 t2 = __hadd2(dq2, sj2);
                __half2 l2 = __hmax2(t2, __hmul2(t2, c02));
                __half2 e2 = __hsub2(l2, mq2);
                uint32_t p;
                asm("ex2.approx.f16x2 %0, %1;" : "=r"(p) : "r"(*(uint32_t*)&e2));
                uint32_t wrd = sMask[q*4 + jt*2 + (lane >> 4)];
                int bit = (lane & 15)*2;
                uint32_t m32 = (((wrd >> bit) & 1u) ? 0x0000FFFFu : 0u)
                             | (((wrd >> bit) & 2u) ? 0xFFFF0000u : 0u);
                p &= m32;
                int kb = jt*128 + lane*4;
                *(uint32_t*)(smem + SP + q*256 + (kb ^ ((q & 7) << 4))) = p;
                __half2 hp = *(__half2*)&p;
                float2 pf = __half22float2(hp);
                lsum += pf.x + pf.y;
            }
            #pragma unroll
            for (int o = 16; o > 0; o >>= 1) lsum += __shfl_xor_sync(0xffffffffu, lsum, o);
            if (lane == 0) sLf[q] += lsum;
        }
        __syncthreads();

        // ---- GEMM quarter: 8 k-steps of 16 ----
        const char* Pb = smem + SP;
        const char* Bb = smem + SB;
        #pragma unroll 2
        for (int ks = 0; ks < 8; ks++) {
            int kb = ks*32 + tc4;
            uint32_t a[2][4], b[4][2];
            #pragma unroll
            for (int mf = 0; mf < 2; mf++) {
                int r0 = mbase + mf*16 + tm, r1 = r0 + 8;
                uint32_t sw0 = (uint32_t)((r0 & 7) << 4);
                uint32_t sw1 = (uint32_t)((r1 & 7) << 4);
                a[mf][0] = *(const uint32_t*)(Pb + r0*256 + (kb ^ sw0));
                a[mf][1] = *(const uint32_t*)(Pb + r1*256 + (kb ^ sw1));
                a[mf][2] = *(const uint32_t*)(Pb + r0*256 + ((kb + 16) ^ sw0));
                a[mf][3] = *(const uint32_t*)(Pb + r1*256 + ((kb + 16) ^ sw1));
            }
            #pragma unroll
            for (int nf = 0; nf < 4; nf++) {
                int n = nbase + nf*8 + tm;
                uint32_t sw = (uint32_t)((n & 7) << 4);
                b[nf][0] = *(const uint32_t*)(Bb + n*256 + (kb ^ sw));
                b[nf][1] = *(const uint32_t*)(Bb + n*256 + ((kb + 16) ^ sw));
            }
            #pragma unroll
            for (int mf = 0; mf < 2; mf++)
                #pragma unroll
                for (int nf = 0; nf < 4; nf++)
                    mma16816(acc[mf][nf], a[mf], b[nf]);
        }
        __syncthreads();   // P/B/mask consumed; safe to restage next quarter
    }

    // ---- normalize + bias -> D (reuses P region; DSTRIDE*4 > 256, full region) ----
    float* D = (float*)(smem + SP);
    #pragma unroll
    for (int mf = 0; mf < 2; mf++) {
        int r = mbase + mf*16 + tm;
        float inv0 = 1.0f / sLf[r];
        float inv8 = 1.0f / sLf[r + 8];
        #pragma unroll
        for (int nf = 0; nf < 4; nf++) {
            int n = nbase + nf*8 + (lane & 3)*2;
            float b0 = sBias[n], b1 = sBias[n + 1];
            *(float2*)&D[r*DSTRIDE + n]       = make_float2(acc[mf][nf][0]*inv0 + b0,
                                                            acc[mf][nf][1]*inv0 + b1);
            *(float2*)&D[(r + 8)*DSTRIDE + n] = make_float2(acc[mf][nf][2]*inv8 + b0,
                                                            acc[mf][nf][3]*inv8 + b1);
        }
    }
    __syncthreads();

    // ---- fused 64->12 GRU input-gate projection ----
    if (tid < 128) {
        int q = tid;
        float g[12];
        #pragma unroll
        for (int k = 0; k < 12; k++) g[k] = sBih[k];
        #pragma unroll 8
        for (int h = 0; h < 64; h += 2) {
            float2 ov = *(const float2*)&D[q*DSTRIDE + h];
            #pragma unroll
            for (int k = 0; k < 12; k++) {
                g[k] = fmaf(sWih[k*64 + h], ov.x, g[k]);
                g[k] = fmaf(sWih[k*64 + h + 1], ov.y, g[k]);
            }
        }
        float* gp = d_gates + ((size_t)bt*NN + mtile*128 + q)*12;
        *(float4*)(gp + 0) = make_float4(g[0], g[1], g[2],  g[3]);
        *(float4*)(gp + 4) = make_float4(g[4], g[5], g[6],  g[7]);
        *(float4*)(gp + 8) = make_float4(g[8], g[9], g[10], g[11]);
    }
}

// ===== K3: fused GRU recurrence + Conv2d(8->12,3x3) + Linear(4->2) ==============
__device__ __forceinline__ float sigm(float v) { return 1.0f / (1.0f + __expf(-v)); }

__global__ void __launch_bounds__(256)
k_tail(const float* __restrict__ W_hh, const float* __restrict__ b_hh,
       const float* __restrict__ conv_W, const float* __restrict__ conv_b,
       const float* __restrict__ out_W,  const float* __restrict__ out_b,
       float* __restrict__ out)
{
    __shared__ float sg[8][130][4];
    __shared__ float sWhh[48], sbhh[12];
    __shared__ float sCW[864], sOW[8], sOB[2], sCB[12];

    int b  = blockIdx.x >> 2;
    int nt = blockIdx.x & 3;
    int tid = threadIdx.x;

    for (int i = tid; i < 864; i += 256) sCW[i] = conv_W[i];
    if (tid < 48) sWhh[tid] = W_hh[tid];
    if (tid < 12) sbhh[tid] = b_hh[tid];
    if (tid < 8)  sOW[tid]  = out_W[tid];
    if (tid < 2)  sOB[tid]  = out_b[tid];
    if (tid >= 16 && tid < 28) sCB[tid - 16] = conv_b[tid - 16];
    for (int i = tid; i < 8*130*4; i += 256) ((float*)sg)[i] = 0.0f;
    __syncthreads();

    if (tid < 130) {
        int n = nt*128 - 1 + tid;
        if (n >= 0 && n < 512) {
            const float* gbase = d_gates + ((size_t)b*4096 + (size_t)n*8)*12;
            float4 c0 = *(const float4*)(gbase + 0);
            float4 c1 = *(const float4*)(gbase + 4);
            float4 c2 = *(const float4*)(gbase + 8);
            float h0 = 0.f, h1 = 0.f, h2 = 0.f, h3 = 0.f;
            #pragma unroll
            for (int s = 0; s < 8; s++) {
                float4 n0, n1, n2;
                if (s < 7) {
                    const float* gnext = gbase + (s + 1)*12;
                    n0 = *(const float4*)(gnext + 0);
                    n1 = *(const float4*)(gnext + 4);
                    n2 = *(const float4*)(gnext + 8);
                }
                float gh[12];
                #pragma unroll
                for (int k = 0; k < 12; k++)
                    gh[k] = sbhh[k] + sWhh[k*4+0]*h0 + sWhh[k*4+1]*h1
                                    + sWhh[k*4+2]*h2 + sWhh[k*4+3]*h3;
                float r0 = sigm(c0.x + gh[0]), r1 = sigm(c0.y + gh[1]);
                float r2 = sigm(c0.z + gh[2]), r3 = sigm(c0.w + gh[3]);
                float z0 = sigm(c1.x + gh[4]), z1 = sigm(c1.y + gh[5]);
                float z2 = sigm(c1.z + gh[6]), z3 = sigm(c1.w + gh[7]);
                float cc0 = tanhf(c2.x + r0*gh[8]),  cc1 = tanhf(c2.y + r1*gh[9]);
                float cc2 = tanhf(c2.z + r2*gh[10]), cc3 = tanhf(c2.w + r3*gh[11]);
                h0 = (1.0f - z0)*cc0 + z0*h0;
                h1 = (1.0f - z1)*cc1 + z1*h1;
                h2 = (1.0f - z2)*cc2 + z2*h2;
                h3 = (1.0f - z3)*cc3 + z3*h3;
                sg[s][tid][0] = h0; sg[s][tid][1] = h1;
                sg[s][tid][2] = h2; sg[s][tid][3] = h3;
                c0 = n0; c1 = n1; c2 = n2;
            }
        }
    }
    __syncthreads();

    #pragma unroll
    for (int k6 = 0; k6 < 6; k6++) {
        int oidx = tid + k6*256;
        int co   = oidx >> 7;
        int nloc = oidx & 127;
        float y0, y1, y2, y3;
        y0 = y1 = y2 = y3 = sCB[co];
        #pragma unroll
        for (int ci = 0; ci < 8; ci++) {
            #pragma unroll
            for (int kh = 0; kh < 3; kh++) {
                const float4 v = *(const float4*)&sg[ci][nloc + kh][0];
                const float* wr = &sCW[(co*8 + ci)*9 + kh*3];
                float w0 = wr[0], w1 = wr[1], w2 = wr[2];
                y0 += v.x*w1 + v.y*w2;
                y1 += v.x*w0 + v.y*w1 + v.z*w2;
                y2 += v.y*w0 + v.z*w1 + v.w*w2;
                y3 += v.z*w0 + v.w*w1;
            }
        }
        float o0 = sOB[0] + y0*sOW[0] + y1*sOW[1] + y2*sOW[2] + y3*sOW[3];
        float o1 = sOB[1] + y0*sOW[4] + y1*sOW[5] + y2*sOW[6] + y3*sOW[7];
        int n = nt*128 + nloc;
        *(float2*)&out[(size_t)((b*12 + co)*512 + n)*2] = make_float2(o0, o1);
    }
}

// ================================ launch =========================================
extern "C" void kernel_launch(void* const* d_in, const int* in_sizes, int n_in,
                              void* d_out, int out_size)
{
    const float* x        = (const float*)d_in[0];
    const float* adj      = (const float*)d_in[1];
    const float* gat_W    = (const float*)d_in[2];
    const float* att_src  = (const float*)d_in[3];
    const float* att_dst  = (const float*)d_in[4];
    const float* gat_bias = (const float*)d_in[5];
    const float* W_ih     = (const float*)d_in[6];
    const float* W_hh     = (const float*)d_in[7];
    const float* b_ih     = (const float*)d_in[8];
    const float* b_hh     = (const float*)d_in[9];
    const float* conv_W   = (const float*)d_in[10];
    const float* conv_b   = (const float*)d_in[11];
    const float* out_W    = (const float*)d_in[12];
    const float* out_b    = (const float*)d_in[13];
    float* out = (float*)d_out;

    cudaFuncSetAttribute(k_attn, cudaFuncAttributeMaxDynamicSharedMemorySize, SME_TOTAL);

    k_proj<<<BTN, 256>>>(x, gat_W, att_src, att_dst);
    k_attn<<<BTN*4, 256, SME_TOTAL>>>(x, adj, gat_W, gat_bias, W_ih, b_ih);
    k_tail<<<BB*4, 256>>>(W_hh, b_hh, conv_W, conv_b, out_W, out_b, out);
}